// round 9
// baseline (speedup 1.0000x reference)
#include <cuda_runtime.h>

#define B_DIM 8
#define H_DIM 8
#define P_DIM 4
#define PB 32
#define FEAT 64
#define EMB 32
#define HIN 96
#define GH 32
#define T_DIM 101770
#define TILE_T 128
#define NUM_TILES ((T_DIM + TILE_T - 1) / TILE_T)   // 796
#define ATT_STRIDE 100   // 96+4: lane-strided LDS.128 conflict-free
#define HMID_STRIDE 36   // 32+4
#define OUT_STRIDE 132   // 128+4
#define GRID_MAIN 148    // 1 big block per SM

// buffer layout (floats)
#define OFF_ATT  0
#define OFF_GEN  (TILE_T * ATT_STRIDE)               // 12800
#define OFF_HMID (OFF_GEN + TILE_T * HMID_STRIDE)    // 17408
#define OFF_GB   (OFF_HMID + PB * HMID_STRIDE)       // 18560
#define OFF_AB   (OFF_GB + TILE_T)                   // 18688
#define BUF_FLOATS (OFF_AB + TILE_T)                 // 18816

// ---------------- device scratch ----------------
__device__ __align__(16) float g_h1[B_DIM * 128];
__device__ __align__(16) float g_hin[PB * HIN];
__device__ __align__(16) float g_hmid[H_DIM * PB * GH];
__device__ __align__(16) float g_gate[B_DIM * H_DIM];

// ---------------- helpers ----------------
static __device__ __forceinline__ unsigned long long ffma2(
    unsigned long long a, unsigned long long b, unsigned long long c) {
    unsigned long long d;
    asm("fma.rn.f32x2 %0, %1, %2, %3;" : "=l"(d) : "l"(a), "l"(b), "l"(c));
    return d;
}
static __device__ __forceinline__ float2 upk(unsigned long long a) {
    float2 f;
    asm("mov.b64 {%0, %1}, %2;" : "=f"(f.x), "=f"(f.y) : "l"(a));
    return f;
}
static __device__ __forceinline__ unsigned smem_u32(const void* p) {
    return (unsigned)__cvta_generic_to_shared(p);
}
#define CP16(dst, src) asm volatile("cp.async.cg.shared.global [%0], [%1], 16;" :: "r"(dst), "l"(src))
#define CP8(dst, src)  asm volatile("cp.async.ca.shared.global [%0], [%1], 8;"  :: "r"(dst), "l"(src))
#define CP_COMMIT()    asm volatile("cp.async.commit_group;")
#define CP_WAIT1()     asm volatile("cp.async.wait_group 1;")

// ---------------- setup 1: h1 = relu(x @ fe_W1^T + fe_b1)  [8,128] -------
__global__ void k_setup1(const float* __restrict__ x,
                         const float* __restrict__ W1,
                         const float* __restrict__ b1) {
    int b = blockIdx.x, j = threadIdx.x;               // 8 blocks x 128 threads
    const float4* xr = (const float4*)(x + b * 784);
    const float4* wr = (const float4*)(W1 + (size_t)j * 784);
    float s0 = 0.f, s1 = 0.f;
#pragma unroll 4
    for (int i = 0; i < 196; i += 2) {
        float4 a0 = xr[i], w0 = wr[i];
        s0 += a0.x * w0.x + a0.y * w0.y + a0.z * w0.z + a0.w * w0.w;
        float4 a1 = xr[i + 1], w1 = wr[i + 1];
        s1 += a1.x * w1.x + a1.y * w1.y + a1.z * w1.z + a1.w * w1.w;
    }
    g_h1[b * 128 + j] = fmaxf(s0 + s1 + b1[j], 0.f);
}

// ---------------- setup 2: feats, gate (softmax over heads), hin ---------
__global__ void k_setup2(const float* __restrict__ W2,
                         const float* __restrict__ b2,
                         const float* __restrict__ embeds,
                         const float* __restrict__ gateW,
                         const float* __restrict__ gateB) {
    __shared__ float sh1[B_DIM * 128];
    __shared__ float sfe[B_DIM * FEAT];
    int tid = threadIdx.x;                              // 128 threads
    for (int i = tid; i < B_DIM * 128; i += 128) sh1[i] = g_h1[i];
    __syncthreads();
    for (int o = tid; o < B_DIM * FEAT; o += 128) {
        int b = o >> 6, f = o & 63;
        const float* w = W2 + f * 128;
        const float* hh = sh1 + b * 128;
        float s = 0.f;
#pragma unroll 8
        for (int k = 0; k < 128; k++) s += hh[k] * w[k];
        sfe[o] = s + b2[f];
    }
    __syncthreads();
    if (tid < B_DIM) {
        int b = tid;
        float l[H_DIM];
        float m = -1e30f;
        for (int h = 0; h < H_DIM; h++) {
            float s = gateB[h];
            for (int f = 0; f < FEAT; f++) s += sfe[b * FEAT + f] * gateW[h * FEAT + f];
            l[h] = s;
            m = fmaxf(m, s);
        }
        float sum = 0.f;
        for (int h = 0; h < H_DIM; h++) { l[h] = expf(l[h] - m); sum += l[h]; }
        float inv = 1.f / sum;
        for (int h = 0; h < H_DIM; h++) g_gate[b * H_DIM + h] = l[h] * inv;
    }
    for (int i = tid; i < PB * HIN; i += 128) {
        int pb = i / HIN, k = i % HIN;
        int p = pb >> 3, bb = pb & 7;
        g_hin[i] = (k < FEAT) ? sfe[bb * FEAT + k] : embeds[p * EMB + (k - FEAT)];
    }
}

// ---------------- setup 3: hmid = relu(hin @ gen_W1^T + gen_b1) ----------
__global__ void k_setup3(const float* __restrict__ W1,
                         const float* __restrict__ b1) {
    int idx = blockIdx.x * blockDim.x + threadIdx.x;    // 32 x 256 = 8192
    int h = idx >> 10, r = idx & 1023, pb = r >> 5, j = r & 31;
    const float4* w = (const float4*)(W1 + (size_t)(h * GH + j) * HIN);
    const float4* hv = (const float4*)(g_hin + pb * HIN);
    float s = 0.f;
#pragma unroll
    for (int i = 0; i < HIN / 4; i++) {
        float4 a = hv[i], ww = w[i];
        s += a.x * ww.x + a.y * ww.y + a.z * ww.z + a.w * ww.w;
    }
    s += b1[h * GH + j];
    g_hmid[(h * PB + pb) * GH + j] = fmaxf(s, 0.f);
}

// ---------------- staging one (tile,h) via cp.async, 256 threads ---------
static __device__ __forceinline__ void stage_iter(
    float* buf, int tile, int h, int tid,
    const float* __restrict__ attW, const float* __restrict__ attB,
    const float* __restrict__ genW2, const float* __restrict__ genB2) {
    const int t0 = tile * TILE_T;
    const int nrow = min(TILE_T, T_DIM - t0);
    const unsigned uAtt  = smem_u32(buf + OFF_ATT);
    const unsigned uGen  = smem_u32(buf + OFF_GEN);
    const unsigned uHmid = smem_u32(buf + OFF_HMID);
    const unsigned uGb   = smem_u32(buf + OFF_GB);
    const unsigned uAb   = smem_u32(buf + OFF_AB);
    const float4* srcA = (const float4*)(attW + (size_t)(h * T_DIM + t0) * HIN);
    const float4* srcG = (const float4*)(genW2 + (size_t)(h * T_DIM + t0) * GH);
    const float4* srcM = (const float4*)(g_hmid + h * PB * GH);

    if (nrow == TILE_T) {
#pragma unroll
        for (int it = 0; it < 12; ++it) {               // att: 3072 f4
            int i = tid + it * 256;
            int r = i / (HIN / 4), c = i % (HIN / 4);
            CP16(uAtt + (unsigned)(r * ATT_STRIDE + c * 4) * 4u, srcA + i);
        }
#pragma unroll
        for (int it = 0; it < 4; ++it) {                // gen: 1024 f4
            int i = tid + it * 256;
            int r = i >> 3, c = i & 7;
            CP16(uGen + (unsigned)(r * HMID_STRIDE + c * 4) * 4u, srcG + i);
        }
        {                                               // hmid: 256 f4
            int r = tid >> 3, c = tid & 7;
            CP16(uHmid + (unsigned)(r * HMID_STRIDE + c * 4) * 4u, srcM + tid);
        }
        if (tid < 64) {
            CP8(uGb + (unsigned)tid * 8u,
                (const char*)(genB2 + (size_t)h * T_DIM + t0) + (size_t)tid * 8);
        } else if (tid < 128) {
            int q = tid - 64;
            CP8(uAb + (unsigned)q * 8u,
                (const char*)(attB + (size_t)h * T_DIM + t0) + (size_t)q * 8);
        }
    } else {
        int nA = nrow * (HIN / 4);
#pragma unroll
        for (int it = 0; it < 12; ++it) {
            int i = tid + it * 256;
            if (i < nA) {
                int r = i / (HIN / 4), c = i % (HIN / 4);
                CP16(uAtt + (unsigned)(r * ATT_STRIDE + c * 4) * 4u, srcA + i);
            }
        }
        int nG = nrow * (GH / 4);
#pragma unroll
        for (int it = 0; it < 4; ++it) {
            int i = tid + it * 256;
            if (i < nG) {
                int r = i >> 3, c = i & 7;
                CP16(uGen + (unsigned)(r * HMID_STRIDE + c * 4) * 4u, srcG + i);
            }
        }
        {
            int r = tid >> 3, c = tid & 7;
            CP16(uHmid + (unsigned)(r * HMID_STRIDE + c * 4) * 4u, srcM + tid);
        }
        if (tid < 64) {
            if (tid * 2 < nrow)
                CP8(uGb + (unsigned)tid * 8u,
                    (const char*)(genB2 + (size_t)h * T_DIM + t0) + (size_t)tid * 8);
        } else if (tid < 128) {
            int q = tid - 64;
            if (q * 2 < nrow)
                CP8(uAb + (unsigned)q * 8u,
                    (const char*)(attB + (size_t)h * T_DIM + t0) + (size_t)q * 8);
        }
    }
}

// ---------------- main fused kernel --------------------------------------
// 256 threads: lane = pb (32), g = tid>>5 (8 t-groups of 16 t each).
// Each thread: 16 t x 1 pb. Per k4: 1 distinct-lane LDS.128 (hin/hmid) +
// 16 broadcast LDS.128 (weights) feeding 32 FFMA2 -> crossbar ratio 0.3125.
__global__ __launch_bounds__(256, 1) void k_main(
    const float* __restrict__ attW, const float* __restrict__ attB,
    const float* __restrict__ genW2, const float* __restrict__ genB2,
    float* __restrict__ out) {
    extern __shared__ float smem[];
    float* bufs[2] = { smem, smem + BUF_FLOATS };
    float* sHin  = smem + 2 * BUF_FLOATS;                // 32*100 = 3200
    float* sGate = sHin + PB * ATT_STRIDE;               // 64
    float* sOut  = sGate + B_DIM * H_DIM;                // 32*132 = 4224

    const int tid = threadIdx.x;
    const int lane = tid & 31;                           // pb index
    const int g = tid >> 5;                              // t-group 0..7
    const int bid = blockIdx.x;

    // hin -> padded smem (stride 100)
    for (int i = tid; i < PB * HIN; i += 256) {
        int r = i / HIN, c = i % HIN;
        sHin[r * ATT_STRIDE + c] = g_hin[i];
    }
    if (tid < B_DIM * H_DIM) sGate[tid] = g_gate[tid];

    const int ntile = (NUM_TILES - bid + GRID_MAIN - 1) / GRID_MAIN;
    const int nit = ntile * H_DIM;

    stage_iter(bufs[0], bid, 0, tid, attW, attB, genW2, genB2);
    CP_COMMIT();

    float comb[16];
    const float gtb = 0.f; (void)gtb;

    for (int it = 0; it < nit; ++it) {
        const int cur = it & 1;
        const int h = it & 7;
        const int tile = bid + (it >> 3) * GRID_MAIN;

        if (it + 1 < nit) {
            const int n2 = it + 1;
            stage_iter(bufs[cur ^ 1], bid + (n2 >> 3) * GRID_MAIN, n2 & 7, tid,
                       attW, attB, genW2, genB2);
        }
        CP_COMMIT();
        CP_WAIT1();
        __syncthreads();

        float* buf = bufs[cur];
        const float* sAtt  = buf + OFF_ATT;
        const float* sGen  = buf + OFF_GEN;
        const float* sHmid = buf + OFF_HMID;
        const float* sGb   = buf + OFF_GB;
        const float* sAb   = buf + OFF_AB;

        if (h == 0) {
#pragma unroll
            for (int tt = 0; tt < 16; ++tt) comb[tt] = 0.f;
        }

        unsigned long long acc[16];
#pragma unroll
        for (int tt = 0; tt < 16; ++tt) acc[tt] = 0ull;

        // ---------- gen GEMM: acc[tt] = hmid[h,pb,:] . genW2[h,t,:] ----------
#pragma unroll
        for (int k4 = 0; k4 < GH / 4; ++k4) {
            ulonglong2 hv = *(const ulonglong2*)&sHmid[lane * HMID_STRIDE + k4 * 4];
#pragma unroll
            for (int tt = 0; tt < 16; ++tt) {
                ulonglong2 w = *(const ulonglong2*)&sGen[(g * 16 + tt) * HMID_STRIDE + k4 * 4];
                acc[tt] = ffma2(hv.x, w.x, acc[tt]);
                acc[tt] = ffma2(hv.y, w.y, acc[tt]);
            }
        }
        float gv[16];
#pragma unroll
        for (int tt = 0; tt < 16; ++tt) {
            float2 f = upk(acc[tt]);
            gv[tt] = f.x + f.y + sGb[g * 16 + tt];
            acc[tt] = 0ull;
        }

        // ---------- att GEMM: acc[tt] = hin[pb,:] . attW[h,t,:] --------------
#pragma unroll 4
        for (int k4 = 0; k4 < HIN / 4; ++k4) {
            ulonglong2 hv = *(const ulonglong2*)&sHin[lane * ATT_STRIDE + k4 * 4];
#pragma unroll
            for (int tt = 0; tt < 16; ++tt) {
                ulonglong2 w = *(const ulonglong2*)&sAtt[(g * 16 + tt) * ATT_STRIDE + k4 * 4];
                acc[tt] = ffma2(hv.x, w.x, acc[tt]);
                acc[tt] = ffma2(hv.y, w.y, acc[tt]);
            }
        }

        // ---------- sigmoid + gated combine: gate[h, b], b = lane&7 ----------
        const float gt = sGate[h * B_DIM + (lane & 7)];
#pragma unroll
        for (int tt = 0; tt < 16; ++tt) {
            float2 f = upk(acc[tt]);
            float a = f.x + f.y + sAb[g * 16 + tt];
            float imp = 1.0f / (1.0f + __expf(-a));
            comb[tt] = fmaf(gt * gv[tt], imp, comb[tt]);
        }

        // ---------- at last head: transpose via smem, coalesced store --------
        if (h == 7) {
#pragma unroll
            for (int tt = 0; tt < 16; ++tt)
                sOut[lane * OUT_STRIDE + g * 16 + tt] = comb[tt];
            __syncthreads();
            const int t0 = tile * TILE_T;
            const int tloc = tid & 127;
            const int t = t0 + tloc;
            if (t < T_DIM) {
#pragma unroll
                for (int r = 0; r < 16; ++r) {
                    int row = (tid >> 7) + r * 2;        // pb row 0..31
                    int p = row >> 3, b = row & 7;
                    out[(size_t)(b * P_DIM + p) * T_DIM + t] =
                        sOut[row * OUT_STRIDE + tloc];
                }
            }
        }
        __syncthreads();   // compute done before this buffer is re-staged
    }
}

// ---------------- launch ----------------
extern "C" void kernel_launch(void* const* d_in, const int* in_sizes, int n_in,
                              void* d_out, int out_size) {
    const float* x      = (const float*)d_in[0];
    const float* fe_W1  = (const float*)d_in[1];
    const float* fe_b1  = (const float*)d_in[2];
    const float* fe_W2  = (const float*)d_in[3];
    const float* fe_b2  = (const float*)d_in[4];
    const float* embeds = (const float*)d_in[5];
    const float* gen_W1 = (const float*)d_in[6];
    const float* gen_b1 = (const float*)d_in[7];
    const float* gen_W2 = (const float*)d_in[8];
    const float* gen_b2 = (const float*)d_in[9];
    const float* att_W  = (const float*)d_in[10];
    const float* att_b  = (const float*)d_in[11];
    const float* gate_W = (const float*)d_in[12];
    const float* gate_b = (const float*)d_in[13];
    float* out = (float*)d_out;

    size_t smem = (size_t)(2 * BUF_FLOATS + PB * ATT_STRIDE + B_DIM * H_DIM +
                           PB * OUT_STRIDE) * sizeof(float);
    cudaFuncSetAttribute(k_main, cudaFuncAttributeMaxDynamicSharedMemorySize, (int)smem);

    k_setup1<<<B_DIM, 128>>>(x, fe_W1, fe_b1);
    k_setup2<<<1, 128>>>(fe_W2, fe_b2, embeds, gate_W, gate_b);
    k_setup3<<<32, 256>>>(gen_W1, gen_b1);
    k_main<<<GRID_MAIN, 256, smem>>>(att_W, att_b, gen_W2, gen_b2, out);
}

// round 11
// speedup vs baseline: 1.7879x; 1.7879x over previous
#include <cuda_runtime.h>

#define B_DIM 8
#define H_DIM 8
#define P_DIM 4
#define PB 32
#define FEAT 64
#define EMB 32
#define HIN 96
#define GH 32
#define T_DIM 101770
#define TILE_T 64
#define NUM_TILES ((T_DIM + TILE_T - 1) / TILE_T)   // 1591
#define ATT_STRIDE 100   // 96+4 floats: lane-strided LDS.128 conflict-free
#define GEN_STRIDE 36    // 32+4
#define GRID_MAIN 296    // 2 blocks per SM

// buffer layout (floats), all 16B-aligned
#define OFF_ATT  0
#define OFF_GEN  (TILE_T * ATT_STRIDE)               // 6400
#define OFF_HMID (OFF_GEN + TILE_T * GEN_STRIDE)     // 8704
#define OFF_GB   (OFF_HMID + PB * GH)                // 9728
#define OFF_AB   (OFF_GB + TILE_T)                   // 9792
#define BUF_FLOATS (OFF_AB + TILE_T)                 // 9856 (39424 B)

// ---------------- device scratch ----------------
__device__ __align__(16) float g_h1[B_DIM * 128];
__device__ __align__(16) float g_hin[PB * HIN];
__device__ __align__(16) float g_hmid[H_DIM * PB * GH];
__device__ __align__(16) float g_gate[B_DIM * H_DIM];

// ---------------- helpers ----------------
static __device__ __forceinline__ unsigned long long ffma2(
    unsigned long long a, unsigned long long b, unsigned long long c) {
    unsigned long long d;
    asm("fma.rn.f32x2 %0, %1, %2, %3;" : "=l"(d) : "l"(a), "l"(b), "l"(c));
    return d;
}
static __device__ __forceinline__ float2 upk(unsigned long long a) {
    float2 f;
    asm("mov.b64 {%0, %1}, %2;" : "=f"(f.x), "=f"(f.y) : "l"(a));
    return f;
}
static __device__ __forceinline__ unsigned smem_u32(const void* p) {
    return (unsigned)__cvta_generic_to_shared(p);
}
#define CP16(dst, src) asm volatile("cp.async.cg.shared.global [%0], [%1], 16;" :: "r"(dst), "l"(src))
#define CP8(dst, src)  asm volatile("cp.async.ca.shared.global [%0], [%1], 8;"  :: "r"(dst), "l"(src))
#define CP4(dst, src)  asm volatile("cp.async.ca.shared.global [%0], [%1], 4;"  :: "r"(dst), "l"(src))
#define CP_COMMIT()    asm volatile("cp.async.commit_group;")
#define CP_WAIT1()     asm volatile("cp.async.wait_group 1;")

// ---------------- setup 1: h1 = relu(x @ fe_W1^T + fe_b1)  [8,128] -------
__global__ void k_setup1(const float* __restrict__ x,
                         const float* __restrict__ W1,
                         const float* __restrict__ b1) {
    int b = blockIdx.x, j = threadIdx.x;
    const float4* xr = (const float4*)(x + b * 784);
    const float4* wr = (const float4*)(W1 + (size_t)j * 784);
    float s0 = 0.f, s1 = 0.f;
#pragma unroll 4
    for (int i = 0; i < 196; i += 2) {
        float4 a0 = xr[i], w0 = wr[i];
        s0 += a0.x * w0.x + a0.y * w0.y + a0.z * w0.z + a0.w * w0.w;
        float4 a1 = xr[i + 1], w1 = wr[i + 1];
        s1 += a1.x * w1.x + a1.y * w1.y + a1.z * w1.z + a1.w * w1.w;
    }
    g_h1[b * 128 + j] = fmaxf(s0 + s1 + b1[j], 0.f);
}

// ---------------- setup 2: feats, gate softmax, hin ----------------------
__global__ void k_setup2(const float* __restrict__ W2,
                         const float* __restrict__ b2,
                         const float* __restrict__ embeds,
                         const float* __restrict__ gateW,
                         const float* __restrict__ gateB) {
    __shared__ float sh1[B_DIM * 128];
    __shared__ float sfe[B_DIM * FEAT];
    int tid = threadIdx.x;
    for (int i = tid; i < B_DIM * 128; i += 128) sh1[i] = g_h1[i];
    __syncthreads();
    for (int o = tid; o < B_DIM * FEAT; o += 128) {
        int b = o >> 6, f = o & 63;
        const float* w = W2 + f * 128;
        const float* hh = sh1 + b * 128;
        float s = 0.f;
#pragma unroll 8
        for (int k = 0; k < 128; k++) s += hh[k] * w[k];
        sfe[o] = s + b2[f];
    }
    __syncthreads();
    if (tid < B_DIM) {
        int b = tid;
        float l[H_DIM];
        float m = -1e30f;
        for (int h = 0; h < H_DIM; h++) {
            float s = gateB[h];
            for (int f = 0; f < FEAT; f++) s += sfe[b * FEAT + f] * gateW[h * FEAT + f];
            l[h] = s;
            m = fmaxf(m, s);
        }
        float sum = 0.f;
        for (int h = 0; h < H_DIM; h++) { l[h] = expf(l[h] - m); sum += l[h]; }
        float inv = 1.f / sum;
        for (int h = 0; h < H_DIM; h++) g_gate[b * H_DIM + h] = l[h] * inv;
    }
    for (int i = tid; i < PB * HIN; i += 128) {
        int pb = i / HIN, k = i % HIN;
        int p = pb >> 3, bb = pb & 7;
        g_hin[i] = (k < FEAT) ? sfe[bb * FEAT + k] : embeds[p * EMB + (k - FEAT)];
    }
}

// ---------------- setup 3: hmid = relu(hin @ gen_W1^T + gen_b1) ----------
__global__ void k_setup3(const float* __restrict__ W1,
                         const float* __restrict__ b1) {
    int idx = blockIdx.x * blockDim.x + threadIdx.x;    // 32 x 256
    int h = idx >> 10, r = idx & 1023, pb = r >> 5, j = r & 31;
    const float4* w = (const float4*)(W1 + (size_t)(h * GH + j) * HIN);
    const float4* hv = (const float4*)(g_hin + pb * HIN);
    float s = 0.f;
#pragma unroll
    for (int i = 0; i < HIN / 4; i++) {
        float4 a = hv[i], ww = w[i];
        s += a.x * ww.x + a.y * ww.y + a.z * ww.z + a.w * ww.w;
    }
    s += b1[h * GH + j];
    g_hmid[(h * PB + pb) * GH + j] = fmaxf(s, 0.f);
}

// ---------------- stage one (tile,h) via cp.async (128 threads) ----------
static __device__ __forceinline__ void stage_iter(
    float* buf, int tile, int h, int tid,
    const float* __restrict__ attW, const float* __restrict__ attB,
    const float* __restrict__ genW2, const float* __restrict__ genB2) {
    const int t0 = tile * TILE_T;
    const int nrow = min(TILE_T, T_DIM - t0);
    const unsigned uAtt  = smem_u32(buf + OFF_ATT);
    const unsigned uGen  = smem_u32(buf + OFF_GEN);
    const unsigned uHmid = smem_u32(buf + OFF_HMID);
    const unsigned uGb   = smem_u32(buf + OFF_GB);
    const unsigned uAb   = smem_u32(buf + OFF_AB);
    const float4* srcA = (const float4*)(attW + (size_t)(h * T_DIM + t0) * HIN);
    const float4* srcG = (const float4*)(genW2 + (size_t)(h * T_DIM + t0) * GH);
    const float4* srcM = (const float4*)(g_hmid + h * PB * GH);

    // hmid: 256 f4, contiguous, 16B-aligned (h*PB*GH*4 = h*4096 bytes)
    CP16(uHmid + (unsigned)tid * 16u, srcM + tid);
    CP16(uHmid + (unsigned)(tid + 128) * 16u, srcM + tid + 128);

    if (nrow == TILE_T) {
#pragma unroll
        for (int it = 0; it < 12; ++it) {               // att: 64*24=1536 f4
            int i = tid + it * 128;
            int r = i / (HIN / 4), c = i % (HIN / 4);
            CP16(uAtt + (unsigned)(r * ATT_STRIDE + c * 4) * 4u, srcA + i);
        }
#pragma unroll
        for (int it = 0; it < 4; ++it) {                // gen: 64*8=512 f4
            int i = tid + it * 128;
            int r = i >> 3, c = i & 7;
            CP16(uGen + (unsigned)(r * GEN_STRIDE + c * 4) * 4u, srcG + i);
        }
        // biases: row base h*T_DIM is only 8B-aligned (T_DIM*4 % 16 == 8)
        // -> must use 8-byte cp.async. 32 thr x 8B = 64 floats each.
        if (tid < 32) {
            CP8(uGb + (unsigned)tid * 8u,
                (const char*)(genB2 + (size_t)h * T_DIM + t0) + (size_t)tid * 8);
        } else if (tid < 64) {
            int q = tid - 32;
            CP8(uAb + (unsigned)q * 8u,
                (const char*)(attB + (size_t)h * T_DIM + t0) + (size_t)q * 8);
        }
    } else {
        int nA = nrow * (HIN / 4);
#pragma unroll
        for (int it = 0; it < 12; ++it) {
            int i = tid + it * 128;
            if (i < nA) {
                int r = i / (HIN / 4), c = i % (HIN / 4);
                CP16(uAtt + (unsigned)(r * ATT_STRIDE + c * 4) * 4u, srcA + i);
            }
        }
        int nG = nrow * (GH / 4);
#pragma unroll
        for (int it = 0; it < 4; ++it) {
            int i = tid + it * 128;
            if (i < nG) {
                int r = i >> 3, c = i & 7;
                CP16(uGen + (unsigned)(r * GEN_STRIDE + c * 4) * 4u, srcG + i);
            }
        }
        if (tid < 64) {                                  // elementwise, exact
            if (tid < nrow)
                CP4(uGb + (unsigned)tid * 4u, genB2 + (size_t)h * T_DIM + t0 + tid);
        } else {
            int q = tid - 64;
            if (q < nrow)
                CP4(uAb + (unsigned)q * 4u, attB + (size_t)h * T_DIM + t0 + q);
        }
    }
}

// ---------------- main fused kernel --------------------------------------
// 128 threads = 32 t-lanes x 4 pb-groups; thread owns 2 t x 8 pb (acc=32 regs).
// Double-buffered cp.async over linearized (tile, h); 2 blocks/SM.
__global__ __launch_bounds__(128, 2) void k_main(
    const float* __restrict__ attW, const float* __restrict__ attB,
    const float* __restrict__ genW2, const float* __restrict__ genB2,
    float* __restrict__ out) {
    extern __shared__ float smem[];
    float* bufs[2] = { smem, smem + BUF_FLOATS };
    float* sHin  = smem + 2 * BUF_FLOATS;                // 32*96
    float* sGate = sHin + PB * HIN;                      // 64

    const int tid = threadIdx.x;
    const int lane = tid & 31;                           // t-lane
    const int wpb = tid >> 5;                            // pb group 0..3
    const int bid = blockIdx.x;

    for (int i = tid; i < PB * HIN; i += 128) sHin[i] = g_hin[i];
    if (tid < B_DIM * H_DIM) sGate[tid] = g_gate[tid];

    const int ntile = (NUM_TILES - bid + GRID_MAIN - 1) / GRID_MAIN;
    const int nit = ntile * H_DIM;

    stage_iter(bufs[0], bid, 0, tid, attW, attB, genW2, genB2);
    CP_COMMIT();

    float comb[2][8];

    for (int it = 0; it < nit; ++it) {
        const int cur = it & 1;
        const int h = it & 7;
        const int tile = bid + (it >> 3) * GRID_MAIN;

        if (it + 1 < nit) {
            const int n2 = it + 1;
            stage_iter(bufs[cur ^ 1], bid + (n2 >> 3) * GRID_MAIN, n2 & 7, tid,
                       attW, attB, genW2, genB2);
        }
        CP_COMMIT();
        CP_WAIT1();
        __syncthreads();

        float* buf = bufs[cur];
        const float* sAtt  = buf + OFF_ATT;
        const float* sGen  = buf + OFF_GEN;
        const float* sHmid = buf + OFF_HMID;
        const float* sGb   = buf + OFF_GB;
        const float* sAb   = buf + OFF_AB;

        if (h == 0) {
#pragma unroll
            for (int jt = 0; jt < 2; ++jt)
#pragma unroll
                for (int j = 0; j < 8; ++j) comb[jt][j] = 0.f;
        }

        unsigned long long acc[2][8];
#pragma unroll
        for (int jt = 0; jt < 2; ++jt)
#pragma unroll
            for (int j = 0; j < 8; ++j) acc[jt][j] = 0ull;

        // ---------- gen GEMM: hmid[h,pb,:] . genW2[h,t,:] ----------
#pragma unroll
        for (int k4 = 0; k4 < GH / 4; ++k4) {
            ulonglong2 w[2];
#pragma unroll
            for (int jt = 0; jt < 2; ++jt)
                w[jt] = *(const ulonglong2*)&sGen[(lane + 32 * jt) * GEN_STRIDE + k4 * 4];
#pragma unroll
            for (int j = 0; j < 8; ++j) {
                ulonglong2 hv = *(const ulonglong2*)&sHmid[(wpb * 8 + j) * GH + k4 * 4];
#pragma unroll
                for (int jt = 0; jt < 2; ++jt) {
                    acc[jt][j] = ffma2(hv.x, w[jt].x, acc[jt][j]);
                    acc[jt][j] = ffma2(hv.y, w[jt].y, acc[jt][j]);
                }
            }
        }
        float gb[2], ab[2];
#pragma unroll
        for (int jt = 0; jt < 2; ++jt) {
            gb[jt] = sGb[lane + 32 * jt];
            ab[jt] = sAb[lane + 32 * jt];
        }
        float gv[2][8];
#pragma unroll
        for (int jt = 0; jt < 2; ++jt)
#pragma unroll
            for (int j = 0; j < 8; ++j) {
                float2 f = upk(acc[jt][j]);
                gv[jt][j] = f.x + f.y + gb[jt];
                acc[jt][j] = 0ull;
            }

        // ---------- att GEMM: hin[pb,:] . attW[h,t,:] ----------
#pragma unroll 4
        for (int k4 = 0; k4 < HIN / 4; ++k4) {
            ulonglong2 w[2];
#pragma unroll
            for (int jt = 0; jt < 2; ++jt)
                w[jt] = *(const ulonglong2*)&sAtt[(lane + 32 * jt) * ATT_STRIDE + k4 * 4];
#pragma unroll
            for (int j = 0; j < 8; ++j) {
                ulonglong2 hv = *(const ulonglong2*)&sHin[(wpb * 8 + j) * HIN + k4 * 4];
#pragma unroll
                for (int jt = 0; jt < 2; ++jt) {
                    acc[jt][j] = ffma2(hv.x, w[jt].x, acc[jt][j]);
                    acc[jt][j] = ffma2(hv.y, w[jt].y, acc[jt][j]);
                }
            }
        }

        // ---------- sigmoid + gated combine: gate[h, b], b = j ----------
        float gt[8];
#pragma unroll
        for (int j = 0; j < 8; ++j) gt[j] = sGate[h * B_DIM + j];
#pragma unroll
        for (int jt = 0; jt < 2; ++jt)
#pragma unroll
            for (int j = 0; j < 8; ++j) {
                float2 f = upk(acc[jt][j]);
                float a = f.x + f.y + ab[jt];
                float imp = 1.0f / (1.0f + __expf(-a));
                comb[jt][j] = fmaf(gt[j] * gv[jt][j], imp, comb[jt][j]);
            }

        // ---------- store at last head (coalesced over lanes) ----------
        if (h == 7) {
            const int t0 = tile * TILE_T;
#pragma unroll
            for (int jt = 0; jt < 2; ++jt) {
                int t = t0 + lane + 32 * jt;
                if (t < T_DIM) {
#pragma unroll
                    for (int j = 0; j < 8; ++j)
                        out[(size_t)(j * P_DIM + wpb) * T_DIM + t] = comb[jt][j];
                }
            }
        }
        __syncthreads();   // compute done before this buffer is re-staged
    }
}

// ---------------- launch ----------------
extern "C" void kernel_launch(void* const* d_in, const int* in_sizes, int n_in,
                              void* d_out, int out_size) {
    const float* x      = (const float*)d_in[0];
    const float* fe_W1  = (const float*)d_in[1];
    const float* fe_b1  = (const float*)d_in[2];
    const float* fe_W2  = (const float*)d_in[3];
    const float* fe_b2  = (const float*)d_in[4];
    const float* embeds = (const float*)d_in[5];
    const float* gen_W1 = (const float*)d_in[6];
    const float* gen_b1 = (const float*)d_in[7];
    const float* gen_W2 = (const float*)d_in[8];
    const float* gen_b2 = (const float*)d_in[9];
    const float* att_W  = (const float*)d_in[10];
    const float* att_b  = (const float*)d_in[11];
    const float* gate_W = (const float*)d_in[12];
    const float* gate_b = (const float*)d_in[13];
    float* out = (float*)d_out;

    size_t smem = (size_t)(2 * BUF_FLOATS + PB * HIN + B_DIM * H_DIM) * sizeof(float);
    cudaFuncSetAttribute(k_main, cudaFuncAttributeMaxDynamicSharedMemorySize, (int)smem);

    k_setup1<<<B_DIM, 128>>>(x, fe_W1, fe_b1);
    k_setup2<<<1, 128>>>(fe_W2, fe_b2, embeds, gate_W, gate_b);
    k_setup3<<<32, 256>>>(gen_W1, gen_b1);
    k_main<<<GRID_MAIN, 128, smem>>>(att_W, att_b, gen_W2, gen_b2, out);
}

// round 12
// speedup vs baseline: 2.0309x; 1.1359x over previous
#include <cuda_runtime.h>

#define B_DIM 8
#define H_DIM 8
#define P_DIM 4
#define PB 32
#define FEAT 64
#define EMB 32
#define HIN 96
#define GH 32
#define T_DIM 101770
#define TILE_T 96
#define JT 3
#define NUM_TILES ((T_DIM + TILE_T - 1) / TILE_T)   // 1061
#define ATT_STRIDE 100   // 96+4: lane-strided LDS.128 conflict-free (stride%32==4)
#define GEN_STRIDE 36    // 32+4
#define GRID_MAIN 296    // 2 blocks per SM

// att double buffer: att tile + att bias (consumed late)
#define OFF_AB      (TILE_T * ATT_STRIDE)            // 9600
#define ABUF_FLOATS (OFF_AB + TILE_T)                // 9696  (38784 B, 16B mult)
// gen single buffer: gen tile + hmid + gen bias (consumed early)
#define OFF_HMID    (TILE_T * GEN_STRIDE)            // 3456
#define OFF_GB      (OFF_HMID + PB * GH)             // 4480
#define GBUF_FLOATS (OFF_GB + TILE_T)                // 4576

// ---------------- device scratch ----------------
__device__ __align__(16) float g_hin[PB * HIN];
__device__ __align__(16) float g_hmid[H_DIM * PB * GH];
__device__ __align__(16) float g_gate[B_DIM * H_DIM];

// ---------------- helpers ----------------
static __device__ __forceinline__ unsigned long long ffma2(
    unsigned long long a, unsigned long long b, unsigned long long c) {
    unsigned long long d;
    asm("fma.rn.f32x2 %0, %1, %2, %3;" : "=l"(d) : "l"(a), "l"(b), "l"(c));
    return d;
}
static __device__ __forceinline__ float2 upk(unsigned long long a) {
    float2 f;
    asm("mov.b64 {%0, %1}, %2;" : "=f"(f.x), "=f"(f.y) : "l"(a));
    return f;
}
static __device__ __forceinline__ unsigned smem_u32(const void* p) {
    return (unsigned)__cvta_generic_to_shared(p);
}
#define CP16(dst, src) asm volatile("cp.async.cg.shared.global [%0], [%1], 16;" :: "r"(dst), "l"(src))
#define CP8(dst, src)  asm volatile("cp.async.ca.shared.global [%0], [%1], 8;"  :: "r"(dst), "l"(src))
#define CP4(dst, src)  asm volatile("cp.async.ca.shared.global [%0], [%1], 4;"  :: "r"(dst), "l"(src))
#define CP_COMMIT()    asm volatile("cp.async.commit_group;")
#define CP_WAIT0()     asm volatile("cp.async.wait_group 0;")

// ---------------- setup A: per-b feats/gate/hin (8 blocks x 128) ---------
__global__ void k_setupA(const float* __restrict__ x,
                         const float* __restrict__ fe_W1, const float* __restrict__ fe_b1,
                         const float* __restrict__ fe_W2, const float* __restrict__ fe_b2,
                         const float* __restrict__ embeds,
                         const float* __restrict__ gateW, const float* __restrict__ gateB) {
    __shared__ float sh1[128];
    __shared__ float sfe[FEAT];
    __shared__ float slog[H_DIM];
    const int b = blockIdx.x, tid = threadIdx.x;

    {   // h1[j] = relu(x[b] . fe_W1[j] + fe_b1[j])
        const float4* xr = (const float4*)(x + b * 784);
        const float4* wr = (const float4*)(fe_W1 + (size_t)tid * 784);
        float s0 = 0.f, s1 = 0.f;
#pragma unroll 4
        for (int i = 0; i < 196; i += 2) {
            float4 a0 = xr[i], w0 = wr[i];
            s0 += a0.x * w0.x + a0.y * w0.y + a0.z * w0.z + a0.w * w0.w;
            float4 a1 = xr[i + 1], w1 = wr[i + 1];
            s1 += a1.x * w1.x + a1.y * w1.y + a1.z * w1.z + a1.w * w1.w;
        }
        sh1[tid] = fmaxf(s0 + s1 + fe_b1[tid], 0.f);
    }
    __syncthreads();
    if (tid < FEAT) {   // feats[b][f]
        const float* w = fe_W2 + tid * 128;
        float s = 0.f;
#pragma unroll 8
        for (int k = 0; k < 128; k++) s += sh1[k] * w[k];
        sfe[tid] = s + fe_b2[tid];
    }
    __syncthreads();
    if (tid < H_DIM) {   // gate logits
        float s = gateB[tid];
        for (int f = 0; f < FEAT; f++) s += sfe[f] * gateW[tid * FEAT + f];
        slog[tid] = s;
    }
    __syncthreads();
    if (tid < H_DIM) {   // softmax (redundant per-thread)
        float m = -1e30f;
        for (int h = 0; h < H_DIM; h++) m = fmaxf(m, slog[h]);
        float sum = 0.f;
        for (int h = 0; h < H_DIM; h++) sum += expf(slog[h] - m);
        g_gate[b * H_DIM + tid] = expf(slog[tid] - m) / sum;
    }
    for (int i = tid; i < P_DIM * HIN; i += 128) {   // hin columns for this b
        int p = i / HIN, k = i % HIN;
        float v = (k < FEAT) ? sfe[k] : embeds[p * EMB + (k - FEAT)];
        g_hin[(p * B_DIM + b) * HIN + k] = v;
    }
}

// ---------------- setup B: hmid = relu(hin @ gen_W1^T + gen_b1) ----------
__global__ void k_setupB(const float* __restrict__ W1,
                         const float* __restrict__ b1) {
    int idx = blockIdx.x * blockDim.x + threadIdx.x;    // 32 x 256
    int h = idx >> 10, r = idx & 1023, pb = r >> 5, j = r & 31;
    const float4* w = (const float4*)(W1 + (size_t)(h * GH + j) * HIN);
    const float4* hv = (const float4*)(g_hin + pb * HIN);
    float s = 0.f;
#pragma unroll
    for (int i = 0; i < HIN / 4; i++) {
        float4 a = hv[i], ww = w[i];
        s += a.x * ww.x + a.y * ww.y + a.z * ww.z + a.w * ww.w;
    }
    s += b1[h * GH + j];
    g_hmid[(h * PB + pb) * GH + j] = fmaxf(s, 0.f);
}

// ---------------- stage att (tile,h) into att buffer ---------------------
static __device__ __forceinline__ void stage_att(
    float* abuf, int tile, int h, int tid,
    const float* __restrict__ attW, const float* __restrict__ attB) {
    const int t0 = tile * TILE_T;
    const int nrow = min(TILE_T, T_DIM - t0);
    const unsigned uA  = smem_u32(abuf);
    const unsigned uAb = smem_u32(abuf + OFF_AB);
    const float4* srcA = (const float4*)(attW + (size_t)(h * T_DIM + t0) * HIN);
    if (nrow == TILE_T) {
#pragma unroll
        for (int it = 0; it < 18; ++it) {               // 96*24 = 2304 f4
            int i = tid + it * 128;
            int r = i / (HIN / 4), c = i % (HIN / 4);
            CP16(uA + (unsigned)(r * ATT_STRIDE + c * 4) * 4u, srcA + i);
        }
        // bias row base only 8B-aligned (T_DIM*4 % 16 == 8) -> CP8
        if (tid < 48)
            CP8(uAb + (unsigned)tid * 8u,
                (const char*)(attB + (size_t)h * T_DIM + t0) + (size_t)tid * 8);
    } else {
        int nA = nrow * (HIN / 4);
#pragma unroll
        for (int it = 0; it < 18; ++it) {
            int i = tid + it * 128;
            if (i < nA) {
                int r = i / (HIN / 4), c = i % (HIN / 4);
                CP16(uA + (unsigned)(r * ATT_STRIDE + c * 4) * 4u, srcA + i);
            }
        }
        if (tid < nrow)
            CP4(uAb + (unsigned)tid * 4u, attB + (size_t)h * T_DIM + t0 + tid);
    }
}

// ---------------- stage gen+hmid+gb (tile,h) into gen buffer -------------
static __device__ __forceinline__ void stage_gen(
    float* gbuf, int tile, int h, int tid,
    const float* __restrict__ genW2, const float* __restrict__ genB2) {
    const int t0 = tile * TILE_T;
    const int nrow = min(TILE_T, T_DIM - t0);
    const unsigned uG  = smem_u32(gbuf);
    const unsigned uM  = smem_u32(gbuf + OFF_HMID);
    const unsigned uGb = smem_u32(gbuf + OFF_GB);
    const float4* srcG = (const float4*)(genW2 + (size_t)(h * T_DIM + t0) * GH);
    const float4* srcM = (const float4*)(g_hmid + h * PB * GH);
    CP16(uM + (unsigned)tid * 16u, srcM + tid);
    CP16(uM + (unsigned)(tid + 128) * 16u, srcM + tid + 128);
    if (nrow == TILE_T) {
#pragma unroll
        for (int it = 0; it < 6; ++it) {                // 96*8 = 768 f4
            int i = tid + it * 128;
            int r = i >> 3, c = i & 7;
            CP16(uG + (unsigned)(r * GEN_STRIDE + c * 4) * 4u, srcG + i);
        }
        if (tid < 48)
            CP8(uGb + (unsigned)tid * 8u,
                (const char*)(genB2 + (size_t)h * T_DIM + t0) + (size_t)tid * 8);
    } else {
        int nG = nrow * (GH / 4);
#pragma unroll
        for (int it = 0; it < 6; ++it) {
            int i = tid + it * 128;
            if (i < nG) {
                int r = i >> 3, c = i & 7;
                CP16(uG + (unsigned)(r * GEN_STRIDE + c * 4) * 4u, srcG + i);
            }
        }
        if (tid < nrow)
            CP4(uGb + (unsigned)tid * 4u, genB2 + (size_t)h * T_DIM + t0 + tid);
    }
}

// ---------------- main fused kernel --------------------------------------
// 128 threads = 32 t-lanes x 4 pb-groups; thread owns 3 t x 8 pb.
// att tile double-buffered, gen/hmid/gb single-buffered (consumed early,
// re-staged after mid-iteration sync while att GEMM runs). 2 blocks/SM.
__global__ __launch_bounds__(128, 2) void k_main(
    const float* __restrict__ attW, const float* __restrict__ attB,
    const float* __restrict__ genW2, const float* __restrict__ genB2,
    float* __restrict__ out) {
    extern __shared__ float smem[];
    float* abufs[2] = { smem, smem + ABUF_FLOATS };
    float* gbuf  = smem + 2 * ABUF_FLOATS;               // 4576
    float* sHin  = gbuf + GBUF_FLOATS;                   // 32*96
    float* sGate = sHin + PB * HIN;                      // 64

    const int tid = threadIdx.x;
    const int lane = tid & 31;                           // t-lane
    const int wpb = tid >> 5;                            // pb group 0..3
    const int bid = blockIdx.x;

    for (int i = tid; i < PB * HIN; i += 128) sHin[i] = g_hin[i];
    if (tid < B_DIM * H_DIM) sGate[tid] = g_gate[tid];

    const int ntile = (NUM_TILES - bid + GRID_MAIN - 1) / GRID_MAIN;
    const int nit = ntile * H_DIM;

    stage_att(abufs[0], bid, 0, tid, attW, attB);
    stage_gen(gbuf, bid, 0, tid, genW2, genB2);
    CP_COMMIT();

    float comb[JT][8];

    for (int it = 0; it < nit; ++it) {
        const int cur = it & 1;
        const int h = it & 7;
        const int tile = bid + (it >> 3) * GRID_MAIN;

        CP_WAIT0();
        __syncthreads();    // data landed; all threads done with abufs[cur] (it-1)

        const float* sAtt  = abufs[cur];
        const float* sAb   = abufs[cur] + OFF_AB;
        const float* sGen  = gbuf;
        const float* sHmid = gbuf + OFF_HMID;
        const float* sGb   = gbuf + OFF_GB;

        if (h == 0) {
#pragma unroll
            for (int jt = 0; jt < JT; ++jt)
#pragma unroll
                for (int j = 0; j < 8; ++j) comb[jt][j] = 0.f;
        }

        unsigned long long acc[JT][8];
#pragma unroll
        for (int jt = 0; jt < JT; ++jt)
#pragma unroll
            for (int j = 0; j < 8; ++j) acc[jt][j] = 0ull;

        // ---------- gen GEMM: hmid[h,pb,:] . genW2[h,t,:] ----------
#pragma unroll
        for (int k4 = 0; k4 < GH / 4; ++k4) {
            ulonglong2 w[JT];
#pragma unroll
            for (int jt = 0; jt < JT; ++jt)
                w[jt] = *(const ulonglong2*)&sGen[(lane + 32 * jt) * GEN_STRIDE + k4 * 4];
#pragma unroll
            for (int j = 0; j < 8; ++j) {
                ulonglong2 hv = *(const ulonglong2*)&sHmid[(wpb * 8 + j) * GH + k4 * 4];
#pragma unroll
                for (int jt = 0; jt < JT; ++jt) {
                    acc[jt][j] = ffma2(hv.x, w[jt].x, acc[jt][j]);
                    acc[jt][j] = ffma2(hv.y, w[jt].y, acc[jt][j]);
                }
            }
        }
        float gb[JT], ab[JT];
#pragma unroll
        for (int jt = 0; jt < JT; ++jt) {
            gb[jt] = sGb[lane + 32 * jt];
            ab[jt] = sAb[lane + 32 * jt];
        }
        float gv[JT][8];
#pragma unroll
        for (int jt = 0; jt < JT; ++jt)
#pragma unroll
            for (int j = 0; j < 8; ++j) {
                float2 f = upk(acc[jt][j]);
                gv[jt][j] = f.x + f.y + gb[jt];
                acc[jt][j] = 0ull;
            }

        __syncthreads();    // everyone done reading gen buffer
        if (it + 1 < nit) { // prefetch next iter while att GEMM runs
            const int n2 = it + 1;
            const int ntile2 = bid + (n2 >> 3) * GRID_MAIN;
            stage_gen(gbuf, ntile2, n2 & 7, tid, genW2, genB2);
            stage_att(abufs[cur ^ 1], ntile2, n2 & 7, tid, attW, attB);
        }
        CP_COMMIT();

        // ---------- att GEMM: hin[pb,:] . attW[h,t,:] ----------
#pragma unroll 4
        for (int k4 = 0; k4 < HIN / 4; ++k4) {
            ulonglong2 w[JT];
#pragma unroll
            for (int jt = 0; jt < JT; ++jt)
                w[jt] = *(const ulonglong2*)&sAtt[(lane + 32 * jt) * ATT_STRIDE + k4 * 4];
#pragma unroll
            for (int j = 0; j < 8; ++j) {
                ulonglong2 hv = *(const ulonglong2*)&sHin[(wpb * 8 + j) * HIN + k4 * 4];
#pragma unroll
                for (int jt = 0; jt < JT; ++jt) {
                    acc[jt][j] = ffma2(hv.x, w[jt].x, acc[jt][j]);
                    acc[jt][j] = ffma2(hv.y, w[jt].y, acc[jt][j]);
                }
            }
        }

        // ---------- sigmoid + gated combine: gate[h, b], b = j ----------
        float gt[8];
#pragma unroll
        for (int j = 0; j < 8; ++j) gt[j] = sGate[h * B_DIM + j];
#pragma unroll
        for (int jt = 0; jt < JT; ++jt)
#pragma unroll
            for (int j = 0; j < 8; ++j) {
                float2 f = upk(acc[jt][j]);
                float a = f.x + f.y + ab[jt];
                float imp = 1.0f / (1.0f + __expf(-a));
                comb[jt][j] = fmaf(gt[j] * gv[jt][j], imp, comb[jt][j]);
            }

        // ---------- store at last head (coalesced over lanes) ----------
        if (h == 7) {
            const int t0 = tile * TILE_T;
#pragma unroll
            for (int jt = 0; jt < JT; ++jt) {
                int t = t0 + lane + 32 * jt;
                if (t < T_DIM) {
#pragma unroll
                    for (int j = 0; j < 8; ++j)
                        out[(size_t)(j * P_DIM + wpb) * T_DIM + t] = comb[jt][j];
                }
            }
        }
    }
}

// ---------------- launch ----------------
extern "C" void kernel_launch(void* const* d_in, const int* in_sizes, int n_in,
                              void* d_out, int out_size) {
    const float* x      = (const float*)d_in[0];
    const float* fe_W1  = (const float*)d_in[1];
    const float* fe_b1  = (const float*)d_in[2];
    const float* fe_W2  = (const float*)d_in[3];
    const float* fe_b2  = (const float*)d_in[4];
    const float* embeds = (const float*)d_in[5];
    const float* gen_W1 = (const float*)d_in[6];
    const float* gen_b1 = (const float*)d_in[7];
    const float* gen_W2 = (const float*)d_in[8];
    const float* gen_b2 = (const float*)d_in[9];
    const float* att_W  = (const float*)d_in[10];
    const float* att_b  = (const float*)d_in[11];
    const float* gate_W = (const float*)d_in[12];
    const float* gate_b = (const float*)d_in[13];
    float* out = (float*)d_out;

    size_t smem = (size_t)(2 * ABUF_FLOATS + GBUF_FLOATS +
                           PB * HIN + B_DIM * H_DIM) * sizeof(float);
    cudaFuncSetAttribute(k_main, cudaFuncAttributeMaxDynamicSharedMemorySize, (int)smem);

    k_setupA<<<B_DIM, 128>>>(x, fe_W1, fe_b1, fe_W2, fe_b2, embeds, gate_W, gate_b);
    k_setupB<<<32, 256>>>(gen_W1, gen_b1);
    k_main<<<GRID_MAIN, 128, smem>>>(att_W, att_b, gen_W2, gen_b2, out);
}

// round 13
// speedup vs baseline: 2.2370x; 1.1015x over previous
#include <cuda_runtime.h>

#define B_DIM 8
#define H_DIM 8
#define P_DIM 4
#define PB 32
#define FEAT 64
#define EMB 32
#define HIN 96
#define GH 32
#define T_DIM 101770
#define TILE_T 96
#define JT 3
#define NUM_TILES ((T_DIM + TILE_T - 1) / TILE_T)   // 1061
#define ATT_STRIDE 100   // 96+4: lane-strided LDS.128 conflict-free
#define GEN_STRIDE 36    // 32+4
#define GRID_MAIN 296    // 2 blocks per SM

// att double buffer: att tile + att bias (consumed late)
#define OFF_AB      (TILE_T * ATT_STRIDE)            // 9600
#define ABUF_FLOATS (OFF_AB + TILE_T)                // 9696
// gen single buffer: gen tile + hmid + gen bias (consumed early)
#define OFF_HMID    (TILE_T * GEN_STRIDE)            // 3456
#define OFF_GB      (OFF_HMID + PB * GH)             // 4480
#define GBUF_FLOATS (OFF_GB + TILE_T)                // 4576

// ---------------- device scratch ----------------
__device__ __align__(16) float g_hin[PB * HIN];
__device__ __align__(16) float g_hmid[H_DIM * PB * GH];
__device__ __align__(16) float g_gate[B_DIM * H_DIM];

// ---------------- helpers ----------------
static __device__ __forceinline__ unsigned long long ffma2(
    unsigned long long a, unsigned long long b, unsigned long long c) {
    unsigned long long d;
    asm("fma.rn.f32x2 %0, %1, %2, %3;" : "=l"(d) : "l"(a), "l"(b), "l"(c));
    return d;
}
static __device__ __forceinline__ float2 upk(unsigned long long a) {
    float2 f;
    asm("mov.b64 {%0, %1}, %2;" : "=f"(f.x), "=f"(f.y) : "l"(a));
    return f;
}
static __device__ __forceinline__ unsigned smem_u32(const void* p) {
    return (unsigned)__cvta_generic_to_shared(p);
}
#define CP16(dst, src) asm volatile("cp.async.cg.shared.global [%0], [%1], 16;" :: "r"(dst), "l"(src))
#define CP8(dst, src)  asm volatile("cp.async.ca.shared.global [%0], [%1], 8;"  :: "r"(dst), "l"(src))
#define CP4(dst, src)  asm volatile("cp.async.ca.shared.global [%0], [%1], 4;"  :: "r"(dst), "l"(src))
#define CP_COMMIT()    asm volatile("cp.async.commit_group;")
#define CP_WAIT0()     asm volatile("cp.async.wait_group 0;")

// ---------------- setup A: per-b feats/gate/hin (8 blocks x 512) ---------
__global__ __launch_bounds__(512) void k_setupA(
    const float* __restrict__ x,
    const float* __restrict__ fe_W1, const float* __restrict__ fe_b1,
    const float* __restrict__ fe_W2, const float* __restrict__ fe_b2,
    const float* __restrict__ embeds,
    const float* __restrict__ gateW, const float* __restrict__ gateB) {
    __shared__ float sh1[128];
    __shared__ float sfe[FEAT];
    __shared__ float slog[H_DIM];
    const int b = blockIdx.x, tid = threadIdx.x;

    {   // h1[j] = relu(x[b] . fe_W1[j] + fe_b1[j]); 4 lanes per j
        const int j = tid >> 2, q = tid & 3;
        const float4* xr = (const float4*)(x + b * 784) + q * 49;
        const float4* wr = (const float4*)(fe_W1 + (size_t)j * 784) + q * 49;
        float s = 0.f;
#pragma unroll 7
        for (int i = 0; i < 49; i++) {
            float4 a = xr[i], w = wr[i];
            s += a.x * w.x + a.y * w.y + a.z * w.z + a.w * w.w;
        }
        s += __shfl_xor_sync(0xffffffffu, s, 1);
        s += __shfl_xor_sync(0xffffffffu, s, 2);
        if (q == 0) sh1[j] = fmaxf(s + fe_b1[j], 0.f);
    }
    __syncthreads();
    {   // feats[b][f]; 8 lanes per f
        const int f = tid >> 3, q = tid & 7;
        const float* w = fe_W2 + f * 128 + q * 16;
        const float* hh = sh1 + q * 16;
        float s = 0.f;
#pragma unroll
        for (int k = 0; k < 16; k++) s += hh[k] * w[k];
        s += __shfl_xor_sync(0xffffffffu, s, 1);
        s += __shfl_xor_sync(0xffffffffu, s, 2);
        s += __shfl_xor_sync(0xffffffffu, s, 4);
        if (q == 0) sfe[f] = s + fe_b2[f];
    }
    __syncthreads();
    if (tid < H_DIM) {   // gate logits
        float s = gateB[tid];
        for (int f = 0; f < FEAT; f++) s += sfe[f] * gateW[tid * FEAT + f];
        slog[tid] = s;
    }
    __syncthreads();
    if (tid < H_DIM) {   // softmax (redundant per-thread)
        float m = -1e30f;
        for (int h = 0; h < H_DIM; h++) m = fmaxf(m, slog[h]);
        float sum = 0.f;
        for (int h = 0; h < H_DIM; h++) sum += expf(slog[h] - m);
        g_gate[b * H_DIM + tid] = expf(slog[tid] - m) / sum;
    }
    for (int i = tid; i < P_DIM * HIN; i += 512) {   // hin columns for this b
        int p = i / HIN, k = i % HIN;
        float v = (k < FEAT) ? sfe[k] : embeds[p * EMB + (k - FEAT)];
        g_hin[(p * B_DIM + b) * HIN + k] = v;
    }
}

// ---------------- setup B: hmid = relu(hin @ gen_W1^T + gen_b1) ----------
__global__ void k_setupB(const float* __restrict__ W1,
                         const float* __restrict__ b1) {
    int idx = blockIdx.x * blockDim.x + threadIdx.x;    // 32 x 256
    int h = idx >> 10, r = idx & 1023, pb = r >> 5, j = r & 31;
    const float4* w = (const float4*)(W1 + (size_t)(h * GH + j) * HIN);
    const float4* hv = (const float4*)(g_hin + pb * HIN);
    float s = 0.f;
#pragma unroll
    for (int i = 0; i < HIN / 4; i++) {
        float4 a = hv[i], ww = w[i];
        s += a.x * ww.x + a.y * ww.y + a.z * ww.z + a.w * ww.w;
    }
    s += b1[h * GH + j];
    g_hmid[(h * PB + pb) * GH + j] = fmaxf(s, 0.f);
}

// ---------------- stage att (tile,h) into att buffer ---------------------
static __device__ __forceinline__ void stage_att(
    float* abuf, int tile, int h, int tid,
    const float* __restrict__ attW, const float* __restrict__ attB) {
    const int t0 = tile * TILE_T;
    const int nrow = min(TILE_T, T_DIM - t0);
    const unsigned uA  = smem_u32(abuf);
    const unsigned uAb = smem_u32(abuf + OFF_AB);
    const float4* srcA = (const float4*)(attW + (size_t)(h * T_DIM + t0) * HIN);
    if (nrow == TILE_T) {
#pragma unroll
        for (int it = 0; it < 18; ++it) {               // 96*24 = 2304 f4
            int i = tid + it * 128;
            int r = i / (HIN / 4), c = i % (HIN / 4);
            CP16(uA + (unsigned)(r * ATT_STRIDE + c * 4) * 4u, srcA + i);
        }
        // bias row base only 8B-aligned (T_DIM*4 % 16 == 8) -> CP8
        if (tid < 48)
            CP8(uAb + (unsigned)tid * 8u,
                (const char*)(attB + (size_t)h * T_DIM + t0) + (size_t)tid * 8);
    } else {
        int nA = nrow * (HIN / 4);
#pragma unroll
        for (int it = 0; it < 18; ++it) {
            int i = tid + it * 128;
            if (i < nA) {
                int r = i / (HIN / 4), c = i % (HIN / 4);
                CP16(uA + (unsigned)(r * ATT_STRIDE + c * 4) * 4u, srcA + i);
            }
        }
        if (tid < nrow)
            CP4(uAb + (unsigned)tid * 4u, attB + (size_t)h * T_DIM + t0 + tid);
    }
}

// ---------------- stage gen+hmid+gb (tile,h) into gen buffer -------------
static __device__ __forceinline__ void stage_gen(
    float* gbuf, int tile, int h, int tid,
    const float* __restrict__ genW2, const float* __restrict__ genB2) {
    const int t0 = tile * TILE_T;
    const int nrow = min(TILE_T, T_DIM - t0);
    const unsigned uG  = smem_u32(gbuf);
    const unsigned uM  = smem_u32(gbuf + OFF_HMID);
    const unsigned uGb = smem_u32(gbuf + OFF_GB);
    const float4* srcG = (const float4*)(genW2 + (size_t)(h * T_DIM + t0) * GH);
    const float4* srcM = (const float4*)(g_hmid + h * PB * GH);
    CP16(uM + (unsigned)tid * 16u, srcM + tid);
    CP16(uM + (unsigned)(tid + 128) * 16u, srcM + tid + 128);
    if (nrow == TILE_T) {
#pragma unroll
        for (int it = 0; it < 6; ++it) {                // 96*8 = 768 f4
            int i = tid + it * 128;
            int r = i >> 3, c = i & 7;
            CP16(uG + (unsigned)(r * GEN_STRIDE + c * 4) * 4u, srcG + i);
        }
        if (tid < 48)
            CP8(uGb + (unsigned)tid * 8u,
                (const char*)(genB2 + (size_t)h * T_DIM + t0) + (size_t)tid * 8);
    } else {
        int nG = nrow * (GH / 4);
#pragma unroll
        for (int it = 0; it < 6; ++it) {
            int i = tid + it * 128;
            if (i < nG) {
                int r = i >> 3, c = i & 7;
                CP16(uG + (unsigned)(r * GEN_STRIDE + c * 4) * 4u, srcG + i);
            }
        }
        if (tid < nrow)
            CP4(uGb + (unsigned)tid * 4u, genB2 + (size_t)h * T_DIM + t0 + tid);
    }
}

// ---------------- main fused kernel --------------------------------------
// 128 threads = 32 t-lanes x 4 pb-groups; thread owns 3 t x 8 pb.
// att double-buffered (prefetched at TOP of iteration -> full-iter overlap);
// gen/hmid/gb single-buffered, re-staged after mid sync. 2 blocks/SM.
__global__ __launch_bounds__(128, 2) void k_main(
    const float* __restrict__ attW, const float* __restrict__ attB,
    const float* __restrict__ genW2, const float* __restrict__ genB2,
    float* __restrict__ out) {
    extern __shared__ float smem[];
    float* abufs[2] = { smem, smem + ABUF_FLOATS };
    float* gbuf  = smem + 2 * ABUF_FLOATS;
    float* sHin  = gbuf + GBUF_FLOATS;                   // 32*96
    float* sGate = sHin + PB * HIN;                      // 64

    const int tid = threadIdx.x;
    const int lane = tid & 31;                           // t-lane
    const int wpb = tid >> 5;                            // pb group 0..3
    const int bid = blockIdx.x;

    for (int i = tid; i < PB * HIN; i += 128) sHin[i] = g_hin[i];
    if (tid < B_DIM * H_DIM) sGate[tid] = g_gate[tid];

    const int ntile = (NUM_TILES - bid + GRID_MAIN - 1) / GRID_MAIN;
    const int nit = ntile * H_DIM;

    stage_att(abufs[0], bid, 0, tid, attW, attB);
    stage_gen(gbuf, bid, 0, tid, genW2, genB2);
    CP_COMMIT();

    float comb[JT][8];

    for (int it = 0; it < nit; ++it) {
        const int cur = it & 1;
        const int h = it & 7;
        const int tile = bid + (it >> 3) * GRID_MAIN;

        CP_WAIT0();
        __syncthreads();    // current att+gen landed; prev iter fully done

        // prefetch next att NOW -> full iteration to land
        if (it + 1 < nit) {
            const int n2 = it + 1;
            stage_att(abufs[cur ^ 1], bid + (n2 >> 3) * GRID_MAIN, n2 & 7,
                      tid, attW, attB);
        }
        CP_COMMIT();

        const float* sAtt  = abufs[cur];
        const float* sAb   = abufs[cur] + OFF_AB;
        const float* sGen  = gbuf;
        const float* sHmid = gbuf + OFF_HMID;
        const float* sGb   = gbuf + OFF_GB;

        if (h == 0) {
#pragma unroll
            for (int jt = 0; jt < JT; ++jt)
#pragma unroll
                for (int j = 0; j < 8; ++j) comb[jt][j] = 0.f;
        }

        unsigned long long acc[JT][8];
#pragma unroll
        for (int jt = 0; jt < JT; ++jt)
#pragma unroll
            for (int j = 0; j < 8; ++j) acc[jt][j] = 0ull;

        // ---------- gen GEMM: hmid[h,pb,:] . genW2[h,t,:] ----------
#pragma unroll
        for (int k4 = 0; k4 < GH / 4; ++k4) {
            ulonglong2 w[JT];
#pragma unroll
            for (int jt = 0; jt < JT; ++jt)
                w[jt] = *(const ulonglong2*)&sGen[(lane + 32 * jt) * GEN_STRIDE + k4 * 4];
#pragma unroll
            for (int j = 0; j < 8; ++j) {
                ulonglong2 hv = *(const ulonglong2*)&sHmid[(wpb * 8 + j) * GH + k4 * 4];
#pragma unroll
                for (int jt = 0; jt < JT; ++jt) {
                    acc[jt][j] = ffma2(hv.x, w[jt].x, acc[jt][j]);
                    acc[jt][j] = ffma2(hv.y, w[jt].y, acc[jt][j]);
                }
            }
        }
        float gb[JT], ab[JT];
#pragma unroll
        for (int jt = 0; jt < JT; ++jt) {
            gb[jt] = sGb[lane + 32 * jt];
            ab[jt] = sAb[lane + 32 * jt];
        }
        float gv[JT][8];
#pragma unroll
        for (int jt = 0; jt < JT; ++jt)
#pragma unroll
            for (int j = 0; j < 8; ++j) {
                float2 f = upk(acc[jt][j]);
                gv[jt][j] = f.x + f.y + gb[jt];
                acc[jt][j] = 0ull;
            }

        __syncthreads();    // everyone done reading gen buffer
        if (it + 1 < nit) { // prefetch next gen while att GEMM runs
            const int n2 = it + 1;
            stage_gen(gbuf, bid + (n2 >> 3) * GRID_MAIN, n2 & 7, tid, genW2, genB2);
        }
        CP_COMMIT();

        // ---------- att GEMM: hin[pb,:] . attW[h,t,:] ----------
#pragma unroll 4
        for (int k4 = 0; k4 < HIN / 4; ++k4) {
            ulonglong2 w[JT];
#pragma unroll
            for (int jt = 0; jt < JT; ++jt)
                w[jt] = *(const ulonglong2*)&sAtt[(lane + 32 * jt) * ATT_STRIDE + k4 * 4];
#pragma unroll
            for (int j = 0; j < 8; ++j) {
                ulonglong2 hv = *(const ulonglong2*)&sHin[(wpb * 8 + j) * HIN + k4 * 4];
#pragma unroll
                for (int jt = 0; jt < JT; ++jt) {
                    acc[jt][j] = ffma2(hv.x, w[jt].x, acc[jt][j]);
                    acc[jt][j] = ffma2(hv.y, w[jt].y, acc[jt][j]);
                }
            }
        }

        // ---------- sigmoid + gated combine: gate[h, b], b = j ----------
        float gt[8];
#pragma unroll
        for (int j = 0; j < 8; ++j) gt[j] = sGate[h * B_DIM + j];
#pragma unroll
        for (int jt = 0; jt < JT; ++jt)
#pragma unroll
            for (int j = 0; j < 8; ++j) {
                float2 f = upk(acc[jt][j]);
                float a = f.x + f.y + ab[jt];
                float imp = 1.0f / (1.0f + __expf(-a));
                comb[jt][j] = fmaf(gt[j] * gv[jt][j], imp, comb[jt][j]);
            }

        // ---------- store at last head (coalesced over lanes) ----------
        if (h == 7) {
            const int t0 = tile * TILE_T;
#pragma unroll
            for (int jt = 0; jt < JT; ++jt) {
                int t = t0 + lane + 32 * jt;
                if (t < T_DIM) {
#pragma unroll
                    for (int j = 0; j < 8; ++j)
                        out[(size_t)(j * P_DIM + wpb) * T_DIM + t] = comb[jt][j];
                }
            }
        }
    }
}

// ---------------- launch ----------------
extern "C" void kernel_launch(void* const* d_in, const int* in_sizes, int n_in,
                              void* d_out, int out_size) {
    const float* x      = (const float*)d_in[0];
    const float* fe_W1  = (const float*)d_in[1];
    const float* fe_b1  = (const float*)d_in[2];
    const float* fe_W2  = (const float*)d_in[3];
    const float* fe_b2  = (const float*)d_in[4];
    const float* embeds = (const float*)d_in[5];
    const float* gen_W1 = (const float*)d_in[6];
    const float* gen_b1 = (const float*)d_in[7];
    const float* gen_W2 = (const float*)d_in[8];
    const float* gen_b2 = (const float*)d_in[9];
    const float* att_W  = (const float*)d_in[10];
    const float* att_b  = (const float*)d_in[11];
    const float* gate_W = (const float*)d_in[12];
    const float* gate_b = (const float*)d_in[13];
    float* out = (float*)d_out;

    size_t smem = (size_t)(2 * ABUF_FLOATS + GBUF_FLOATS +
                           PB * HIN + B_DIM * H_DIM) * sizeof(float);
    cudaFuncSetAttribute(k_main, cudaFuncAttributeMaxDynamicSharedMemorySize, (int)smem);

    k_setupA<<<B_DIM, 512>>>(x, fe_W1, fe_b1, fe_W2, fe_b2, embeds, gate_W, gate_b);
    k_setupB<<<32, 256>>>(gen_W1, gen_b1);
    k_main<<<GRID_MAIN, 128, smem>>>(att_W, att_b, gen_W2, gen_b2, out);
}

// round 14
// speedup vs baseline: 2.2519x; 1.0067x over previous
#include <cuda_runtime.h>

#define B_DIM 8
#define H_DIM 8
#define P_DIM 4
#define PB 32
#define FEAT 64
#define EMB 32
#define HIN 96
#define GH 32
#define T_DIM 101770
#define TILE_T 96
#define JT 3
#define NUM_TILES ((T_DIM + TILE_T - 1) / TILE_T)   // 1061
#define ATT_STRIDE 100   // 96+4: lane-strided LDS.128 conflict-free (t*25 mod 32 distinct)
#define GEN_STRIDE 36    // 32+4 (t*9 mod 32 distinct)
#define GRID_MAIN 296    // 2 blocks per SM

// att double buffer: att weight tile only
#define ABUF_FLOATS (TILE_T * ATT_STRIDE)            // 9600
// gen single buffer: gen tile + hmid
#define OFF_HMID    (TILE_T * GEN_STRIDE)            // 3456
#define GBUF_FLOATS (OFF_HMID + PB * GH)             // 4480

// ---------------- device scratch ----------------
__device__ __align__(16) float g_h1[B_DIM * 128];
__device__ __align__(16) float g_hin[PB * HIN];
__device__ __align__(16) float g_hmid[H_DIM * PB * GH];
__device__ __align__(16) float g_gate[B_DIM * H_DIM];

// ---------------- helpers ----------------
static __device__ __forceinline__ unsigned long long ffma2(
    unsigned long long a, unsigned long long b, unsigned long long c) {
    unsigned long long d;
    asm("fma.rn.f32x2 %0, %1, %2, %3;" : "=l"(d) : "l"(a), "l"(b), "l"(c));
    return d;
}
static __device__ __forceinline__ float2 upk(unsigned long long a) {
    float2 f;
    asm("mov.b64 {%0, %1}, %2;" : "=f"(f.x), "=f"(f.y) : "l"(a));
    return f;
}
static __device__ __forceinline__ unsigned smem_u32(const void* p) {
    return (unsigned)__cvta_generic_to_shared(p);
}
#define CP16(dst, src) asm volatile("cp.async.cg.shared.global [%0], [%1], 16;" :: "r"(dst), "l"(src))
#define CP_COMMIT()    asm volatile("cp.async.commit_group;")
#define CP_WAIT0()     asm volatile("cp.async.wait_group 0;")

// ---------------- kA1: h1 = relu(x @ fe_W1^T + fe_b1), 64 blocks ---------
// block = (jc, b); 128 threads = 16 j x 8 lanes; shuffle-reduce over lanes.
__global__ __launch_bounds__(128) void kA1(
    const float* __restrict__ x,
    const float* __restrict__ W1, const float* __restrict__ b1) {
    const int jc = blockIdx.x >> 3, b = blockIdx.x & 7;
    const int j = jc * 16 + (threadIdx.x >> 3), q = threadIdx.x & 7;
    const float2* xr = (const float2*)(x + b * 784) + q * 49;
    const float2* wr = (const float2*)(W1 + (size_t)j * 784) + q * 49;
    float s = 0.f;
#pragma unroll 7
    for (int i = 0; i < 49; i++) {
        float2 a = xr[i], w = wr[i];
        s += a.x * w.x + a.y * w.y;
    }
    s += __shfl_xor_sync(0xffffffffu, s, 1);
    s += __shfl_xor_sync(0xffffffffu, s, 2);
    s += __shfl_xor_sync(0xffffffffu, s, 4);
    if (q == 0) g_h1[b * 128 + j] = fmaxf(s + b1[j], 0.f);
}

// ---------------- kA2: feats, gate softmax, hin (8 blocks x 128) ---------
__global__ __launch_bounds__(128) void kA2(
    const float* __restrict__ fe_W2, const float* __restrict__ fe_b2,
    const float* __restrict__ embeds,
    const float* __restrict__ gateW, const float* __restrict__ gateB) {
    __shared__ float sh1[128];
    __shared__ float sfe[FEAT];
    __shared__ float slog[H_DIM];
    const int b = blockIdx.x, tid = threadIdx.x;

    sh1[tid] = g_h1[b * 128 + tid];
    __syncthreads();
    {   // feats[b][f]; 2 lanes per f
        const int f = tid >> 1, half = tid & 1;
        const float* w = fe_W2 + f * 128 + half * 64;
        const float* hh = sh1 + half * 64;
        float s = 0.f;
#pragma unroll 16
        for (int k = 0; k < 64; k++) s += hh[k] * w[k];
        s += __shfl_xor_sync(0xffffffffu, s, 1);
        if (half == 0) sfe[f] = s + fe_b2[f];
    }
    __syncthreads();
    if (tid < H_DIM) {   // gate logits
        float s = gateB[tid];
        for (int f = 0; f < FEAT; f++) s += sfe[f] * gateW[tid * FEAT + f];
        slog[tid] = s;
    }
    __syncthreads();
    if (tid < H_DIM) {   // softmax (redundant per-thread)
        float m = -1e30f;
        for (int h = 0; h < H_DIM; h++) m = fmaxf(m, slog[h]);
        float sum = 0.f;
        for (int h = 0; h < H_DIM; h++) sum += expf(slog[h] - m);
        g_gate[b * H_DIM + tid] = expf(slog[tid] - m) / sum;
    }
    for (int i = tid; i < P_DIM * HIN; i += 128) {   // hin columns for this b
        int p = i / HIN, k = i % HIN;
        float v = (k < FEAT) ? sfe[k] : embeds[p * EMB + (k - FEAT)];
        g_hin[(p * B_DIM + b) * HIN + k] = v;
    }
}

// ---------------- kB: hmid = relu(hin @ gen_W1^T + gen_b1) ---------------
__global__ void kB(const float* __restrict__ W1,
                   const float* __restrict__ b1) {
    int idx = blockIdx.x * blockDim.x + threadIdx.x;    // 32 x 256
    int h = idx >> 10, r = idx & 1023, pb = r >> 5, j = r & 31;
    const float4* w = (const float4*)(W1 + (size_t)(h * GH + j) * HIN);
    const float4* hv = (const float4*)(g_hin + pb * HIN);
    float s = 0.f;
#pragma unroll
    for (int i = 0; i < HIN / 4; i++) {
        float4 a = hv[i], ww = w[i];
        s += a.x * ww.x + a.y * ww.y + a.z * ww.z + a.w * ww.w;
    }
    s += b1[h * GH + j];
    g_hmid[(h * PB + pb) * GH + j] = fmaxf(s, 0.f);
}

// ---------------- stage att weight tile (tile,h) via cp.async ------------
static __device__ __forceinline__ void stage_att(
    float* abuf, int tile, int h, int tid,
    const float* __restrict__ attW) {
    const int t0 = tile * TILE_T;
    const int nrow = min(TILE_T, T_DIM - t0);
    const unsigned uA = smem_u32(abuf);
    const float4* srcA = (const float4*)(attW + (size_t)(h * T_DIM + t0) * HIN);
    if (nrow == TILE_T) {
#pragma unroll
        for (int it = 0; it < 18; ++it) {               // 96*24 = 2304 f4
            int i = tid + it * 128;
            int r = i / (HIN / 4), c = i % (HIN / 4);
            CP16(uA + (unsigned)(r * ATT_STRIDE + c * 4) * 4u, srcA + i);
        }
    } else {
        int nA = nrow * (HIN / 4);
#pragma unroll
        for (int it = 0; it < 18; ++it) {
            int i = tid + it * 128;
            if (i < nA) {
                int r = i / (HIN / 4), c = i % (HIN / 4);
                CP16(uA + (unsigned)(r * ATT_STRIDE + c * 4) * 4u, srcA + i);
            }
        }
    }
}

// ---------------- stage gen+hmid (tile,h) into gen buffer ----------------
static __device__ __forceinline__ void stage_gen(
    float* gbuf, int tile, int h, int tid,
    const float* __restrict__ genW2) {
    const int t0 = tile * TILE_T;
    const int nrow = min(TILE_T, T_DIM - t0);
    const unsigned uG = smem_u32(gbuf);
    const unsigned uM = smem_u32(gbuf + OFF_HMID);
    const float4* srcG = (const float4*)(genW2 + (size_t)(h * T_DIM + t0) * GH);
    const float4* srcM = (const float4*)(g_hmid + h * PB * GH);
    CP16(uM + (unsigned)tid * 16u, srcM + tid);
    CP16(uM + (unsigned)(tid + 128) * 16u, srcM + tid + 128);
    if (nrow == TILE_T) {
#pragma unroll
        for (int it = 0; it < 6; ++it) {                // 96*8 = 768 f4
            int i = tid + it * 128;
            int r = i >> 3, c = i & 7;
            CP16(uG + (unsigned)(r * GEN_STRIDE + c * 4) * 4u, srcG + i);
        }
    } else {
        int nG = nrow * (GH / 4);
#pragma unroll
        for (int it = 0; it < 6; ++it) {
            int i = tid + it * 128;
            if (i < nG) {
                int r = i >> 3, c = i & 7;
                CP16(uG + (unsigned)(r * GEN_STRIDE + c * 4) * 4u, srcG + i);
            }
        }
    }
}

// ---------------- main fused kernel --------------------------------------
// 128 threads = 32 t-lanes x 4 pb-groups; thread owns 3 t x 8 pb.
// att double-buffered (prefetched at TOP of iter); gen/hmid single-buffered,
// re-staged after mid sync; biases via predicated LDG. 2 blocks/SM.
__global__ __launch_bounds__(128, 2) void k_main(
    const float* __restrict__ attW, const float* __restrict__ attB,
    const float* __restrict__ genW2, const float* __restrict__ genB2,
    float* __restrict__ out) {
    extern __shared__ float smem[];
    float* abufs[2] = { smem, smem + ABUF_FLOATS };
    float* gbuf  = smem + 2 * ABUF_FLOATS;
    float* sHin  = gbuf + GBUF_FLOATS;                   // 32*96
    float* sGate = sHin + PB * HIN;                      // 64

    const int tid = threadIdx.x;
    const int lane = tid & 31;                           // t-lane
    const int wpb = tid >> 5;                            // pb group 0..3
    const int bid = blockIdx.x;

    for (int i = tid; i < PB * HIN; i += 128) sHin[i] = g_hin[i];
    if (tid < B_DIM * H_DIM) sGate[tid] = g_gate[tid];

    const int ntile = (NUM_TILES - bid + GRID_MAIN - 1) / GRID_MAIN;
    const int nit = ntile * H_DIM;

    stage_att(abufs[0], bid, 0, tid, attW);
    stage_gen(gbuf, bid, 0, tid, genW2);
    CP_COMMIT();

    float comb[JT][8];

    for (int it = 0; it < nit; ++it) {
        const int cur = it & 1;
        const int h = it & 7;
        const int tile = bid + (it >> 3) * GRID_MAIN;
        const int t0 = tile * TILE_T;

        CP_WAIT0();
        __syncthreads();    // current att+gen landed; prev iter fully done

        // issue bias loads early (LDG, coalesced, land before use)
        float gb[JT], ab[JT];
#pragma unroll
        for (int jt = 0; jt < JT; ++jt) {
            int t = t0 + lane + 32 * jt;
            bool v = t < T_DIM;
            gb[jt] = v ? __ldg(genB2 + (size_t)h * T_DIM + t) : 0.f;
            ab[jt] = v ? __ldg(attB + (size_t)h * T_DIM + t) : 0.f;
        }

        // prefetch next att NOW -> full iteration to land
        if (it + 1 < nit) {
            const int n2 = it + 1;
            stage_att(abufs[cur ^ 1], bid + (n2 >> 3) * GRID_MAIN, n2 & 7,
                      tid, attW);
        }
        CP_COMMIT();

        const float* sAtt  = abufs[cur];
        const float* sGen  = gbuf;
        const float* sHmid = gbuf + OFF_HMID;

        if (h == 0) {
#pragma unroll
            for (int jt = 0; jt < JT; ++jt)
#pragma unroll
                for (int j = 0; j < 8; ++j) comb[jt][j] = 0.f;
        }

        unsigned long long acc[JT][8];
#pragma unroll
        for (int jt = 0; jt < JT; ++jt)
#pragma unroll
            for (int j = 0; j < 8; ++j) acc[jt][j] = 0ull;

        // ---------- gen GEMM: hmid[h,pb,:] . genW2[h,t,:] ----------
#pragma unroll
        for (int k4 = 0; k4 < GH / 4; ++k4) {
            ulonglong2 w[JT];
#pragma unroll
            for (int jt = 0; jt < JT; ++jt)
                w[jt] = *(const ulonglong2*)&sGen[(lane + 32 * jt) * GEN_STRIDE + k4 * 4];
#pragma unroll
            for (int j = 0; j < 8; ++j) {
                ulonglong2 hv = *(const ulonglong2*)&sHmid[(wpb * 8 + j) * GH + k4 * 4];
#pragma unroll
                for (int jt = 0; jt < JT; ++jt) {
                    acc[jt][j] = ffma2(hv.x, w[jt].x, acc[jt][j]);
                    acc[jt][j] = ffma2(hv.y, w[jt].y, acc[jt][j]);
                }
            }
        }
        float gv[JT][8];
#pragma unroll
        for (int jt = 0; jt < JT; ++jt)
#pragma unroll
            for (int j = 0; j < 8; ++j) {
                float2 f = upk(acc[jt][j]);
                gv[jt][j] = f.x + f.y + gb[jt];
                acc[jt][j] = 0ull;
            }

        __syncthreads();    // everyone done reading gen buffer
        if (it + 1 < nit) { // prefetch next gen while att GEMM runs
            const int n2 = it + 1;
            stage_gen(gbuf, bid + (n2 >> 3) * GRID_MAIN, n2 & 7, tid, genW2);
        }
        CP_COMMIT();

        // ---------- att GEMM: hin[pb,:] . attW[h,t,:] ----------
#pragma unroll 4
        for (int k4 = 0; k4 < HIN / 4; ++k4) {
            ulonglong2 w[JT];
#pragma unroll
            for (int jt = 0; jt < JT; ++jt)
                w[jt] = *(const ulonglong2*)&sAtt[(lane + 32 * jt) * ATT_STRIDE + k4 * 4];
#pragma unroll
            for (int j = 0; j < 8; ++j) {
                ulonglong2 hv = *(const ulonglong2*)&sHin[(wpb * 8 + j) * HIN + k4 * 4];
#pragma unroll
                for (int jt = 0; jt < JT; ++jt) {
                    acc[jt][j] = ffma2(hv.x, w[jt].x, acc[jt][j]);
                    acc[jt][j] = ffma2(hv.y, w[jt].y, acc[jt][j]);
                }
            }
        }

        // ---------- sigmoid + gated combine: gate[h, b], b = j ----------
        float gt[8];
#pragma unroll
        for (int j = 0; j < 8; ++j) gt[j] = sGate[h * B_DIM + j];
#pragma unroll
        for (int jt = 0; jt < JT; ++jt)
#pragma unroll
            for (int j = 0; j < 8; ++j) {
                float2 f = upk(acc[jt][j]);
                float a = f.x + f.y + ab[jt];
                float imp = 1.0f / (1.0f + __expf(-a));
                comb[jt][j] = fmaf(gt[j] * gv[jt][j], imp, comb[jt][j]);
            }

        // ---------- store at last head (coalesced over lanes) ----------
        if (h == 7) {
#pragma unroll
            for (int jt = 0; jt < JT; ++jt) {
                int t = t0 + lane + 32 * jt;
                if (t < T_DIM) {
#pragma unroll
                    for (int j = 0; j < 8; ++j)
                        out[(size_t)(j * P_DIM + wpb) * T_DIM + t] = comb[jt][j];
                }
            }
        }
    }
}

// ---------------- launch ----------------
extern "C" void kernel_launch(void* const* d_in, const int* in_sizes, int n_in,
                              void* d_out, int out_size) {
    const float* x      = (const float*)d_in[0];
    const float* fe_W1  = (const float*)d_in[1];
    const float* fe_b1  = (const float*)d_in[2];
    const float* fe_W2  = (const float*)d_in[3];
    const float* fe_b2  = (const float*)d_in[4];
    const float* embeds = (const float*)d_in[5];
    const float* gen_W1 = (const float*)d_in[6];
    const float* gen_b1 = (const float*)d_in[7];
    const float* gen_W2 = (const float*)d_in[8];
    const float* gen_b2 = (const float*)d_in[9];
    const float* att_W  = (const float*)d_in[10];
    const float* att_b  = (const float*)d_in[11];
    const float* gate_W = (const float*)d_in[12];
    const float* gate_b = (const float*)d_in[13];
    float* out = (float*)d_out;

    size_t smem = (size_t)(2 * ABUF_FLOATS + GBUF_FLOATS +
                           PB * HIN + B_DIM * H_DIM) * sizeof(float);
    cudaFuncSetAttribute(k_main, cudaFuncAttributeMaxDynamicSharedMemorySize, (int)smem);

    kA1<<<64, 128>>>(x, fe_W1, fe_b1);
    kA2<<<B_DIM, 128>>>(fe_W2, fe_b2, embeds, gate_W, gate_b);
    kB<<<32, 256>>>(gen_W1, gen_b1);
    k_main<<<GRID_MAIN, 128, smem>>>(att_W, att_b, gen_W2, gen_b2, out);
}